// round 15
// baseline (speedup 1.0000x reference)
#include <cuda_runtime.h>
#include <cuda_fp16.h>
#include <cstdint>

#define N_NODES 200000
#define HID 32

// ---------------- scratch (static device globals; no allocation) ----------
__device__ int   g_deg[N_NODES];
__device__ float g_dinv[N_NODES];
__device__ float g_acc1[N_NODES];
__device__ float g_h2 [N_NODES * HID];   // h2 PRE-SCALED by dinv[n]
__device__ float g_acc2[N_NODES * HID];
__device__ float g_x2 [N_NODES * HID];

// ---------------- GCN stages ------------------------------------------------
__global__ void k_init(const float* __restrict__ ec, float* __restrict__ out_edge, int E) {
    int i = blockIdx.x * blockDim.x + threadIdx.x;
    if (i < N_NODES * HID / 4) ((float4*)g_acc2)[i] = make_float4(0.f, 0.f, 0.f, 0.f);
    if (i < N_NODES) { g_deg[i] = 0; g_acc1[i] = 0.f; }
    if (i < E) out_edge[i] = ec[i];
}
__global__ void k_deg(const int* __restrict__ dst, int E) {
    int e = blockIdx.x * blockDim.x + threadIdx.x;
    if (e < E) atomicAdd(&g_deg[dst[e]], 1);
}
__global__ void k_dinv() {
    int n = blockIdx.x * blockDim.x + threadIdx.x;
    if (n < N_NODES) g_dinv[n] = rsqrtf((float)(g_deg[n] + 1));
}
__global__ void k_acc1(const int* __restrict__ src, const int* __restrict__ dst, int E) {
    int e = blockIdx.x * blockDim.x + threadIdx.x;
    if (e < E) atomicAdd(&g_acc1[dst[e]], g_dinv[src[e]]);
}
__global__ void k_node1(const float* __restrict__ W1, const float* __restrict__ b1,
                        const float* __restrict__ W2) {
    __shared__ float sW1[HID], sB1[HID], sW2[HID * HID];
    for (int i = threadIdx.x; i < HID; i += blockDim.x) { sW1[i] = W1[i]; sB1[i] = b1[i]; }
    for (int i = threadIdx.x; i < HID * HID; i += blockDim.x) sW2[i] = W2[i];
    __syncthreads();
    int n = blockIdx.x * blockDim.x + threadIdx.x;
    if (n >= N_NODES) return;
    float dv = g_dinv[n];
    float s1 = dv * (g_acc1[n] + dv);
    float x1[HID];
#pragma unroll
    for (int k = 0; k < HID; k++) x1[k] = fmaxf(fmaf(sW1[k], s1, sB1[k]), 0.f);
    float h2[HID];
#pragma unroll
    for (int j = 0; j < HID; j++) h2[j] = 0.f;
#pragma unroll
    for (int i = 0; i < HID; i++) {
        float xi = x1[i];
#pragma unroll
        for (int j = 0; j < HID; j++) h2[j] = fmaf(xi, sW2[i * HID + j], h2[j]);
    }
    float4* o = (float4*)(g_h2 + (size_t)n * HID);
#pragma unroll
    for (int q = 0; q < 8; q++)
        o[q] = make_float4(h2[4 * q] * dv, h2[4 * q + 1] * dv,
                           h2[4 * q + 2] * dv, h2[4 * q + 3] * dv);
}
__global__ void k_msg(const int* __restrict__ src, const int* __restrict__ dst, int E) {
    int idx = blockIdx.x * blockDim.x + threadIdx.x;
    int e = idx >> 3, k = (idx & 7) << 2;
    if (e >= E) return;
    int s = src[e], d = dst[e];
    float nrm = g_dinv[d];
    float4 v = *(const float4*)(g_h2 + (size_t)s * HID + k);
    float* p = g_acc2 + (size_t)d * HID + k;
    asm volatile("red.global.add.v4.f32 [%0], {%1,%2,%3,%4};"
                 :: "l"(p), "f"(v.x * nrm), "f"(v.y * nrm), "f"(v.z * nrm), "f"(v.w * nrm)
                 : "memory");
}
__global__ void k_node2(const float* __restrict__ b2) {
    int i = blockIdx.x * blockDim.x + threadIdx.x;
    if (i >= N_NODES * HID) return;
    int n = i >> 5, k = i & 31;
    float dv = g_dinv[n];
    g_x2[i] = fmaxf(g_acc2[i] + g_h2[i] * dv + b2[k], 0.f);
}

// ---------------- stage 7: triangle MLP, fp16 MMA + cp.async pipeline -------
#define WPB  4
#define TILE 16
#define SAH  56     // sA row stride in halves (112B)
#define SHH  72     // sH row stride in halves (144B)
// per-warp region layout (bytes): sA 1792 | sH 2304 | sPF 6144 | sIdx 192
#define WB_A    0
#define WB_H    1792
#define WB_PF   4096
#define WB_IDX  10240
#define WARP_BYTES 10432
// block smem layout
#define OFF_W1H  0                    // 3*8*32 uint2 = 6144 B
#define OFF_B1B  6144
#define OFF_B2B  6400
#define OFF_B3B  6528
#define OFF_STG  6560
#define SMEM_BYTES (OFF_STG + WPB * WARP_BYTES)   // 48288

__device__ __forceinline__ uint32_t packh2(float lo, float hi) {
    __half2 h = __floats2half2_rn(lo, hi);
    return *(uint32_t*)&h;
}
__device__ __forceinline__ void mma_f16(
    float& c0, float& c1, float& c2, float& c3,
    uint32_t a0, uint32_t a1, uint32_t a2, uint32_t a3,
    uint32_t b0, uint32_t b1)
{
    asm volatile(
        "mma.sync.aligned.m16n8k16.row.col.f32.f16.f16.f32 "
        "{%0,%1,%2,%3},{%4,%5,%6,%7},{%8,%9},{%0,%1,%2,%3};"
        : "+f"(c0), "+f"(c1), "+f"(c2), "+f"(c3)
        : "r"(a0), "r"(a1), "r"(a2), "r"(a3), "r"(b0), "r"(b1));
}
__device__ __forceinline__ void cp16(uint32_t dst, const void* src) {
    asm volatile("cp.async.cg.shared.global [%0], [%1], 16;" :: "r"(dst), "l"(src) : "memory");
}

__global__ void __launch_bounds__(WPB * 32, 4) k_tri(
    const float* __restrict__ t12, const float* __restrict__ t13, const float* __restrict__ t23,
    const int* __restrict__ c12, const int* __restrict__ c13, const int* __restrict__ c23,
    const float* __restrict__ ec,
    const float* __restrict__ Wm1, const float* __restrict__ bm1,
    const float* __restrict__ Wm2, const float* __restrict__ bm2,
    const float* __restrict__ Wm3, const float* __restrict__ bm3,
    float* __restrict__ out_edge,
    float* __restrict__ o12, float* __restrict__ o13, float* __restrict__ o23, int T)
{
    extern __shared__ char smem[];
    uint2* sW1h = (uint2*)(smem + OFF_W1H);
    float* sB1 = (float*)(smem + OFF_B1B);
    float* sB2 = (float*)(smem + OFF_B2B);
    float* sB3 = (float*)(smem + OFF_B3B);
    char*  stage = smem + OFF_STG;

    const int tid = threadIdx.x;

    // ---- W1 fragment table as half2 pairs (1/3 folded into rows 3..34) ----
    for (int i = tid; i < 3 * 8 * 32; i += blockDim.x) {
        int kt = i >> 8, nt = (i >> 5) & 7, j = i & 31;
        int q = j >> 3, g = j & 7;
        int col = nt * 8 + g;
        int r0 = kt * 16 + 2 * q;
        float v[4];
#pragma unroll
        for (int u = 0; u < 4; u++) {
            int r = r0 + (u >> 1) * 8 + (u & 1);
            float w = (r < 38) ? Wm1[r * 64 + col] : 0.f;
            if (r >= 3 && r < 35) w *= (1.f / 3.f);
            v[u] = w;
        }
        sW1h[i] = make_uint2(packh2(v[0], v[1]), packh2(v[2], v[3]));
    }
    // zero all staging (sA pad cols stay zero forever)
    for (int i = tid; i < WPB * WARP_BYTES / 4; i += blockDim.x)
        ((uint32_t*)stage)[i] = 0;
    if (tid < 64) sB1[tid] = bm1[tid];
    if (tid < 32) sB2[tid] = bm2[tid];
    if (tid < 4)  sB3[tid] = (tid < 3) ? bm3[tid] : 0.f;
    __syncthreads();

    const int wid  = tid >> 5;
    const int lane = tid & 31;
    const int grp  = lane >> 2;
    const int qd   = lane & 3;
    const int fj   = (qd << 3) + grp;
    char* wbase = stage + wid * WARP_BYTES;
    __half* sAh = (__half*)(wbase + WB_A);     // [16][56]
    __half* sHh = (__half*)(wbase + WB_H);     // [16][72]
    float*  sPF = (float*)(wbase + WB_PF);     // [48][32]
    int*    sIdx = (int*)(wbase + WB_IDX);     // [48]
    const uint32_t pfAddr = (uint32_t)__cvta_generic_to_shared(sPF);

    // ---- loop-invariant weight fragments in registers --------------------
    uint2 w2r[4][4];
#pragma unroll
    for (int kt = 0; kt < 4; kt++)
#pragma unroll
        for (int nt = 0; nt < 4; nt++) {
            int r0 = kt * 16 + 2 * qd, c = nt * 8 + grp;
            w2r[kt][nt] = make_uint2(
                packh2(Wm2[r0 * 32 + c],       Wm2[(r0 + 1) * 32 + c]),
                packh2(Wm2[(r0 + 8) * 32 + c], Wm2[(r0 + 9) * 32 + c]));
        }
    uint2 w3r[2];
#pragma unroll
    for (int kt = 0; kt < 2; kt++) {
        int r0 = kt * 16 + 2 * qd;
        float v0 = (grp < 3) ? Wm3[r0 * 3 + grp]       : 0.f;
        float v1 = (grp < 3) ? Wm3[(r0 + 1) * 3 + grp] : 0.f;
        float v2 = (grp < 3) ? Wm3[(r0 + 8) * 3 + grp] : 0.f;
        float v3 = (grp < 3) ? Wm3[(r0 + 9) * 3 + grp] : 0.f;
        w3r[kt] = make_uint2(packh2(v0, v1), packh2(v2, v3));
    }
    const float b3c0 = (2 * qd     < 3) ? sB3[2 * qd]     : 0.f;
    const float b3c1 = (2 * qd + 1 < 3) ? sB3[2 * qd + 1] : 0.f;

    const int ntiles = (T + TILE - 1) / TILE;
    const int gstride = gridDim.x * WPB;
    int tile = blockIdx.x * WPB + wid;
    if (tile >= ntiles) return;

    // ---- prologue: load tile0 scalars, prefetch tile0 rows ----------------
    int cia = 0, cib = 0, cic = 0;
    float cf12 = 0.f, cf13 = 0.f, cf23 = 0.f, cea = 0.f, ceb = 0.f, cec = 0.f;
    if (lane < TILE) {
        int t = tile * TILE + lane;
        if (t < T) {
            cia = c12[t]; cib = c13[t]; cic = c23[t];
            cf12 = t12[t]; cf13 = t13[t]; cf23 = t23[t];
            cea = __ldg(ec + cia); ceb = __ldg(ec + cib); cec = __ldg(ec + cic);
        }
        sIdx[lane] = cia; sIdx[16 + lane] = cib; sIdx[32 + lane] = cic;
    }
    __syncwarp();
#pragma unroll
    for (int i = 0; i < 12; i++) {
        int task = lane + 32 * i;
        int row = task >> 3, seg = task & 7;
        cp16(pfAddr + (uint32_t)(row * 32 + seg * 4) * 4,
             g_x2 + (size_t)sIdx[row] * HID + seg * 4);
    }
    asm volatile("cp.async.commit_group;" ::: "memory");

    // load tile1 scalars
    int nia = 0, nib = 0, nic = 0;
    float nf12 = 0.f, nf13 = 0.f, nf23 = 0.f, nea = 0.f, neb = 0.f, nec = 0.f;
    {
        int tl = tile + gstride;
        if (lane < TILE && tl < ntiles) {
            int t = tl * TILE + lane;
            if (t < T) {
                nia = c12[t]; nib = c13[t]; nic = c23[t];
                nf12 = t12[t]; nf13 = t13[t]; nf23 = t23[t];
                nea = __ldg(ec + nia); neb = __ldg(ec + nib); nec = __ldg(ec + nic);
            }
        }
    }

    // ---- main pipelined loop ----------------------------------------------
    for (; tile < ntiles; ) {
        const bool have_next = (tile + gstride) < ntiles;

        // 0. current prefetch must be complete
        asm volatile("cp.async.wait_group 0;" ::: "memory");
        __syncwarp();

        // 1. build sA: scalars + row sums from sPF
        if (lane < TILE) {
            __half* row = sAh + lane * SAH;
            row[0]  = __float2half(cf12);
            row[1]  = __float2half(cf13);
            row[2]  = __float2half(cf23);
            row[35] = __float2half(cea);
            row[36] = __float2half(ceb);
            row[37] = __float2half(cec);
        }
#pragma unroll
        for (int r = 0; r < TILE; r++)
            sAh[r * SAH + 3 + lane] = __float2half(
                sPF[r * 32 + lane] + sPF[(16 + r) * 32 + lane] + sPF[(32 + r) * 32 + lane]);
        __syncwarp();   // sums consumed from sPF; sA visible warp-wide

        // 2. issue next tile's prefetch into sPF
        if (have_next) {
            if (lane < TILE) {
                sIdx[lane] = nia; sIdx[16 + lane] = nib; sIdx[32 + lane] = nic;
            }
            __syncwarp();
#pragma unroll
            for (int i = 0; i < 12; i++) {
                int task = lane + 32 * i;
                int row = task >> 3, seg = task & 7;
                cp16(pfAddr + (uint32_t)(row * 32 + seg * 4) * 4,
                     g_x2 + (size_t)sIdx[row] * HID + seg * 4);
            }
            asm volatile("cp.async.commit_group;" ::: "memory");
        }

        // 3. load tile+2 scalars (two tiles of slack)
        int pia = 0, pib = 0, pic = 0;
        float pf12 = 0.f, pf13 = 0.f, pf23 = 0.f, pea = 0.f, peb = 0.f, pec = 0.f;
        {
            int tl = tile + 2 * gstride;
            if (lane < TILE && tl < ntiles) {
                int t = tl * TILE + lane;
                if (t < T) {
                    pia = c12[t]; pib = c13[t]; pic = c23[t];
                    pf12 = t12[t]; pf13 = t13[t]; pf23 = t23[t];
                    pea = __ldg(ec + pia); peb = __ldg(ec + pib); pec = __ldg(ec + pic);
                }
            }
        }

        // 4a. layer 1: [16x48(40)] @ [48x64] fp16
        float a1[8][4];
#pragma unroll
        for (int nt = 0; nt < 8; nt++) {
            float2 bb = *(const float2*)(sB1 + nt * 8 + 2 * qd);
            a1[nt][0] = bb.x; a1[nt][1] = bb.y; a1[nt][2] = bb.x; a1[nt][3] = bb.y;
        }
#pragma unroll
        for (int kt = 0; kt < 3; kt++) {
            uint32_t A0 = *(const uint32_t*)(sAh + grp * SAH + kt * 16 + 2 * qd);
            uint32_t A1 = *(const uint32_t*)(sAh + (grp + 8) * SAH + kt * 16 + 2 * qd);
            uint32_t A2 = *(const uint32_t*)(sAh + grp * SAH + kt * 16 + 2 * qd + 8);
            uint32_t A3 = *(const uint32_t*)(sAh + (grp + 8) * SAH + kt * 16 + 2 * qd + 8);
#pragma unroll
            for (int nt = 0; nt < 8; nt++) {
                uint2 b = sW1h[(kt * 8 + nt) * 32 + fj];
                mma_f16(a1[nt][0], a1[nt][1], a1[nt][2], a1[nt][3], A0, A1, A2, A3, b.x, b.y);
            }
        }
#pragma unroll
        for (int nt = 0; nt < 8; nt++) {
            int colc = nt * 8 + 2 * qd;
            *(uint32_t*)(sHh + grp * SHH + colc) =
                packh2(fmaxf(a1[nt][0], 0.f), fmaxf(a1[nt][1], 0.f));
            *(uint32_t*)(sHh + (grp + 8) * SHH + colc) =
                packh2(fmaxf(a1[nt][2], 0.f), fmaxf(a1[nt][3], 0.f));
        }
        __syncwarp();

        // 4b. layer 2: [16x64] @ [64x32] fp16 (W2 in registers)
        float a2[4][4];
#pragma unroll
        for (int nt = 0; nt < 4; nt++) {
            float2 bb = *(const float2*)(sB2 + nt * 8 + 2 * qd);
            a2[nt][0] = bb.x; a2[nt][1] = bb.y; a2[nt][2] = bb.x; a2[nt][3] = bb.y;
        }
#pragma unroll
        for (int kt = 0; kt < 4; kt++) {
            uint32_t H0 = *(const uint32_t*)(sHh + grp * SHH + kt * 16 + 2 * qd);
            uint32_t H1 = *(const uint32_t*)(sHh + (grp + 8) * SHH + kt * 16 + 2 * qd);
            uint32_t H2 = *(const uint32_t*)(sHh + grp * SHH + kt * 16 + 2 * qd + 8);
            uint32_t H3 = *(const uint32_t*)(sHh + (grp + 8) * SHH + kt * 16 + 2 * qd + 8);
#pragma unroll
            for (int nt = 0; nt < 4; nt++)
                mma_f16(a2[nt][0], a2[nt][1], a2[nt][2], a2[nt][3],
                        H0, H1, H2, H3, w2r[kt][nt].x, w2r[kt][nt].y);
        }
        __syncwarp();   // sA rows consumed by L1; safe to restage h2 into sA
#pragma unroll
        for (int nt = 0; nt < 4; nt++) {
            int colc = nt * 8 + 2 * qd;
            *(uint32_t*)(sAh + grp * SAH + colc) =
                packh2(fmaxf(a2[nt][0], 0.f), fmaxf(a2[nt][1], 0.f));
            *(uint32_t*)(sAh + (grp + 8) * SAH + colc) =
                packh2(fmaxf(a2[nt][2], 0.f), fmaxf(a2[nt][3], 0.f));
        }
        __syncwarp();

        // 4c. layer 3: [16x32] @ [32x8(3)] fp16 (W3 in registers)
        float d0 = b3c0, d1 = b3c1, d2 = b3c0, d3 = b3c1;
#pragma unroll
        for (int kt = 0; kt < 2; kt++) {
            uint32_t A0 = *(const uint32_t*)(sAh + grp * SAH + kt * 16 + 2 * qd);
            uint32_t A1 = *(const uint32_t*)(sAh + (grp + 8) * SAH + kt * 16 + 2 * qd);
            uint32_t A2 = *(const uint32_t*)(sAh + grp * SAH + kt * 16 + 2 * qd + 8);
            uint32_t A3 = *(const uint32_t*)(sAh + (grp + 8) * SAH + kt * 16 + 2 * qd + 8);
            mma_f16(d0, d1, d2, d3, A0, A1, A2, A3, w3r[kt].x, w3r[kt].y);
        }
        float* sD = (float*)sHh;
        if (2 * qd < 3)     { sD[grp * 4 + 2 * qd]     = d0; sD[(grp + 8) * 4 + 2 * qd]     = d2; }
        if (2 * qd + 1 < 3) { sD[grp * 4 + 2 * qd + 1] = d1; sD[(grp + 8) * 4 + 2 * qd + 1] = d3; }
        __syncwarp();

        // 5. epilogue (current tile)
        if (lane < TILE) {
            int t = tile * TILE + lane;
            if (t < T) {
                float4 dd = *(const float4*)(sD + lane * 4);
                o12[t] = cf12 - dd.x;
                o13[t] = cf13 - dd.y;
                o23[t] = cf23 - dd.z;
                atomicAdd(out_edge + cia, dd.x);
                atomicAdd(out_edge + cib, dd.y);
                atomicAdd(out_edge + cic, dd.z);
            }
        }
        __syncwarp();

        // 6. rotate pipeline registers
        cia = nia; cib = nib; cic = nic;
        cf12 = nf12; cf13 = nf13; cf23 = nf23;
        cea = nea; ceb = neb; cec = nec;
        nia = pia; nib = pib; nic = pic;
        nf12 = pf12; nf13 = pf13; nf23 = pf23;
        nea = pea; neb = peb; nec = pec;
        tile += gstride;
    }
}

// ---------------- launcher ----------------------------------------------------
extern "C" void kernel_launch(void* const* d_in, const int* in_sizes, int n_in,
                              void* d_out, int out_size) {
    const float* edge_costs = (const float*)d_in[0];
    const float* t12 = (const float*)d_in[1];
    const float* t13 = (const float*)d_in[2];
    const float* t23 = (const float*)d_in[3];
    const int*   c12 = (const int*)d_in[4];
    const int*   c13 = (const int*)d_in[5];
    const int*   c23 = (const int*)d_in[6];
    const int*   eidx = (const int*)d_in[8];
    const float* W1  = (const float*)d_in[10];
    const float* b1  = (const float*)d_in[11];
    const float* W2  = (const float*)d_in[12];
    const float* b2  = (const float*)d_in[13];
    const float* Wm1 = (const float*)d_in[14];
    const float* bm1 = (const float*)d_in[15];
    const float* Wm2 = (const float*)d_in[16];
    const float* bm2 = (const float*)d_in[17];
    const float* Wm3 = (const float*)d_in[18];
    const float* bm3 = (const float*)d_in[19];

    int E = in_sizes[0];       // 200000
    int T = in_sizes[1];       // 2000000
    const int* src = eidx;
    const int* dst = eidx + E;

    float* out_edge = (float*)d_out;
    float* o12 = out_edge + E;
    float* o13 = o12 + T;
    float* o23 = o13 + T;

    const int B = 256;
    k_init <<<(N_NODES * HID + B - 1) / B, B>>>(edge_costs, out_edge, E);
    k_deg  <<<(E + B - 1) / B, B>>>(dst, E);
    k_dinv <<<(N_NODES + B - 1) / B, B>>>();
    k_acc1 <<<(E + B - 1) / B, B>>>(src, dst, E);
    k_node1<<<(N_NODES + B - 1) / B, B>>>(W1, b1, W2);
    k_msg  <<<((size_t)E * 8 + B - 1) / B, B>>>(src, dst, E);
    k_node2<<<(N_NODES * HID + B - 1) / B, B>>>(b2);

    cudaFuncSetAttribute(k_tri, cudaFuncAttributeMaxDynamicSharedMemorySize, SMEM_BYTES);
    k_tri<<<2368, WPB * 32, SMEM_BYTES>>>(t12, t13, t23, c12, c13, c23, edge_costs,
                                          Wm1, bm1, Wm2, bm2, Wm3, bm3,
                                          out_edge, o12, o13, o23, T);
}